// round 13
// baseline (speedup 1.0000x reference)
#include <cuda_runtime.h>
#include <cuda_bf16.h>
#include <cstdint>
#include <math_constants.h>

#define B_   4
#define T_   4096
#define EMB_ 768
#define HS_  64
#define BT_  (B_*T_)

// bf16 split operands. K/Q/V natural [row][h]; W converted to [k][n0..191].
__device__ __nv_bfloat16 g_Khi[BT_*HS_];
__device__ __nv_bfloat16 g_Klo[BT_*HS_];
__device__ __nv_bfloat16 g_Qhi[BT_*HS_];
__device__ __nv_bfloat16 g_Qlo[BT_*HS_];
__device__ __nv_bfloat16 g_Vhi[BT_*HS_];
__device__ __nv_bfloat16 g_Vlo[BT_*HS_];
__device__ __nv_bfloat16 g_Whi[EMB_*192];
__device__ __nv_bfloat16 g_Wlo[EMB_*192];
// split-s partials (unnormalized): O and l per split
__device__ float g_Op[2][BT_*HS_];
__device__ float g_lp[2][BT_];

__device__ __forceinline__ uint32_t smem_u32(const void* p) {
    uint32_t a;
    asm("{ .reg .u64 t; cvta.to.shared.u64 t, %1; cvt.u32.u64 %0, t; }"
        : "=r"(a) : "l"(p));
    return a;
}
__device__ __forceinline__ void ldsm_x4(uint32_t* r, uint32_t addr) {
    asm volatile("ldmatrix.sync.aligned.m8n8.x4.shared.b16 {%0,%1,%2,%3}, [%4];"
        : "=r"(r[0]), "=r"(r[1]), "=r"(r[2]), "=r"(r[3]) : "r"(addr));
}
__device__ __forceinline__ void ldsm_x4_t(uint32_t* r, uint32_t addr) {
    asm volatile("ldmatrix.sync.aligned.m8n8.x4.trans.shared.b16 {%0,%1,%2,%3}, [%4];"
        : "=r"(r[0]), "=r"(r[1]), "=r"(r[2]), "=r"(r[3]) : "r"(addr));
}
__device__ __forceinline__ void mma16816(float* d, const uint32_t* a, const uint32_t* b) {
    asm volatile("mma.sync.aligned.m16n8k16.row.col.f32.bf16.bf16.f32 "
        "{%0,%1,%2,%3},{%4,%5,%6,%7},{%8,%9},{%0,%1,%2,%3};"
        : "+f"(d[0]), "+f"(d[1]), "+f"(d[2]), "+f"(d[3])
        : "r"(a[0]), "r"(a[1]), "r"(a[2]), "r"(a[3]), "r"(b[0]), "r"(b[1]));
}
__device__ __forceinline__ uint32_t pack_bf16(float a, float b) {
    return (uint32_t)__bfloat16_as_ushort(__float2bfloat16(a)) |
           ((uint32_t)__bfloat16_as_ushort(__float2bfloat16(b)) << 16);
}

// ===========================================================================
// W converter
// ===========================================================================
__global__ __launch_bounds__(256) void wconv_kernel(
    const float* __restrict__ Wk, const float* __restrict__ Wq,
    const float* __restrict__ Wv)
{
    const int e = blockIdx.x * 256 + threadIdx.x;
    const int k = e >> 6, n = e & 63;
#pragma unroll
    for (int mat = 0; mat < 3; ++mat) {
        const float* src = (mat == 0) ? Wk : (mat == 1) ? Wq : Wv;
        float v = src[e];
        __nv_bfloat16 h = __float2bfloat16(v);
        size_t o = (size_t)k * 192 + mat * 64 + n;
        g_Whi[o] = h;
        g_Wlo[o] = __float2bfloat16(v - __bfloat162float(h));
    }
}

// ===========================================================================
// Tensorized projection (unchanged from R8/R9 pass).
// ===========================================================================
#define OXH 0u
#define OXL 16384u
#define OWT 32768u
#define PROJ_SMEM 81920u

__global__ __launch_bounds__(256) void proj_kernel(
    const float* __restrict__ x,
    const float* __restrict__ bk, const float* __restrict__ bq,
    const float* __restrict__ bv)
{
    extern __shared__ char sm[];
    const uint32_t sb = smem_u32(sm);
    const int tid = threadIdx.x, lane = tid & 31, wid = tid >> 5;
    const int m0 = (wid & 3) * 32, n0 = (wid >> 2) * 96;
    const int row0 = blockIdx.x * 128;

    float acc[2][12][4];
#pragma unroll
    for (int a = 0; a < 2; ++a)
#pragma unroll
        for (int b = 0; b < 12; ++b)
#pragma unroll
            for (int c = 0; c < 4; ++c) acc[a][b][c] = 0.f;

    for (int kc = 0; kc < 12; ++kc) {
        __syncthreads();
#pragma unroll
        for (int hl = 0; hl < 2; ++hl) {
            const __nv_bfloat16* gw = hl ? g_Wlo : g_Whi;
#pragma unroll
            for (int i = 0; i < 6; ++i) {
                int idx = tid + i * 256;
                int k = idx / 24, nc = (idx % 24) * 8;
                uint4 v = *(const uint4*)(gw + (size_t)(kc*64 + k) * 192 + nc);
                int mat = nc >> 6, ln = nc & 63;
                uint32_t dst = OWT + (uint32_t)mat*16384u + (uint32_t)hl*8192u
                             + (uint32_t)k*128u
                             + (uint32_t)((((ln >> 3) ^ (k & 7))) << 4);
                *(uint4*)(sm + dst) = v;
            }
        }
#pragma unroll
        for (int i = 0; i < 8; ++i) {
            int idx = tid + i * 256;
            int r = idx >> 4, c4 = (idx & 15) * 4;
            float4 v = *(const float4*)(x + (size_t)(row0 + r) * EMB_ + kc*64 + c4);
            __nv_bfloat16 hx = __float2bfloat16(v.x), hy = __float2bfloat16(v.y);
            __nv_bfloat16 hz = __float2bfloat16(v.z), hw = __float2bfloat16(v.w);
            uint32_t h01 = (uint32_t)__bfloat16_as_ushort(hx) |
                           ((uint32_t)__bfloat16_as_ushort(hy) << 16);
            uint32_t h23 = (uint32_t)__bfloat16_as_ushort(hz) |
                           ((uint32_t)__bfloat16_as_ushort(hw) << 16);
            uint32_t l01 = pack_bf16(v.x - __bfloat162float(hx),
                                     v.y - __bfloat162float(hy));
            uint32_t l23 = pack_bf16(v.z - __bfloat162float(hz),
                                     v.w - __bfloat162float(hw));
            uint32_t off = (uint32_t)r * 128u
                         + (uint32_t)((((c4 >> 3) ^ (r & 7))) << 4)
                         + (uint32_t)((c4 & 7) * 2);
            *(uint2*)(sm + OXH + off) = make_uint2(h01, h23);
            *(uint2*)(sm + OXL + off) = make_uint2(l01, l23);
        }
        __syncthreads();

#pragma unroll
        for (int ks = 0; ks < 4; ++ks) {
            uint32_t ah[2][4], al[2][4];
#pragma unroll
            for (int mt = 0; mt < 2; ++mt) {
                int arow = m0 + mt*16 + (lane & 15);
                int kg = 2*ks + (lane >> 4);
                uint32_t aoff = (uint32_t)arow*128u
                              + (uint32_t)(((kg ^ (arow & 7))) << 4);
                ldsm_x4(ah[mt], sb + OXH + aoff);
                ldsm_x4(al[mt], sb + OXL + aoff);
            }
            const int g = lane >> 3, rr = lane & 7;
            const int krow = ks*16 + ((g & 1) << 3) + rr;
#pragma unroll
            for (int grp = 0; grp < 6; ++grp) {
                int hglob = n0 + grp*16 + ((g >> 1) << 3);
                int mat = hglob >> 6, lc = hglob & 63;
                uint32_t base = OWT + (uint32_t)mat * 16384u;
                uint32_t voff = (uint32_t)krow*128u
                              + (uint32_t)((((lc >> 3) ^ (krow & 7))) << 4);
                uint32_t wh[4], wl[4];
                ldsm_x4_t(wh, sb + base + voff);
                ldsm_x4_t(wl, sb + base + 8192u + voff);
#pragma unroll
                for (int mt = 0; mt < 2; ++mt)
#pragma unroll
                    for (int jj = 0; jj < 2; ++jj) {
                        float* d = acc[mt][grp*2 + jj];
                        mma16816(d, ah[mt], wh + jj*2);
                        mma16816(d, al[mt], wh + jj*2);
                        mma16816(d, ah[mt], wl + jj*2);
                    }
            }
        }
    }

#pragma unroll
    for (int nj = 0; nj < 12; ++nj) {
        const int c0 = n0 + nj*8 + 2*(lane & 3);
        const int mat = c0 >> 6, lc = c0 & 63;
        const float* bp = (mat == 0) ? bk : (mat == 1) ? bq : bv;
        const float b0 = bp[lc], b1 = bp[lc + 1];
        __nv_bfloat16* hp = (mat == 0) ? g_Khi : (mat == 1) ? g_Qhi : g_Vhi;
        __nv_bfloat16* lp = (mat == 0) ? g_Klo : (mat == 1) ? g_Qlo : g_Vlo;
#pragma unroll
        for (int mt = 0; mt < 2; ++mt)
#pragma unroll
            for (int h = 0; h < 2; ++h) {
                const int r = row0 + m0 + mt*16 + (lane >> 2) + h*8;
                float v0 = acc[mt][nj][h*2 + 0] + b0;
                float v1 = acc[mt][nj][h*2 + 1] + b1;
                __nv_bfloat16 h0 = __float2bfloat16(v0);
                __nv_bfloat16 h1 = __float2bfloat16(v1);
                uint32_t hv = (uint32_t)__bfloat16_as_ushort(h0) |
                              ((uint32_t)__bfloat16_as_ushort(h1) << 16);
                uint32_t lv = pack_bf16(v0 - __bfloat162float(h0),
                                        v1 - __bfloat162float(h1));
                size_t o = (size_t)r * HS_ + lc;
                *(uint32_t*)(hp + o) = hv;
                *(uint32_t*)(lp + o) = lv;
            }
    }
}

// ===========================================================================
// Attention: R9 GEMM structure (256 thr, m16n32/warp) + split-s partials.
// grid.x = 128: bx>>1 -> tile (descending), bx&1 -> s-split half.
// ===========================================================================
#define OKHI  0u
#define OKLO  8192u
#define OBUF(b) (16384u + (uint32_t)(b) * 32768u)
#define OPHI  81920u
#define OPLO  90112u
#define ATTN_SMEM 98304u

__device__ __forceinline__ void ld_tile(char* sm, uint32_t dst,
                                        const __nv_bfloat16* __restrict__ src) {
#pragma unroll
    for (int i = 0; i < 2; ++i) {
        int idx = threadIdx.x + i * 256;
        int r = idx >> 3, cc = idx & 7;
        uint32_t off = (uint32_t)r * 128u + (uint32_t)((cc ^ (r & 7)) << 4);
        *(uint4*)(sm + dst + off) = *(const uint4*)(src + (size_t)r * HS_ + cc * 8);
    }
}

__device__ __forceinline__ void gemm_split(uint32_t sb, uint32_t aHi, uint32_t aLo,
                                           uint32_t bHi, uint32_t bLo,
                                           int m0, int n0, float S[4][4])
{
    const int lane = threadIdx.x & 31;
    const int arow  = m0 + (lane & 15);
    const int brow0 = n0 + (lane & 7) + ((lane >> 4) << 3);
    const int brow1 = brow0 + 16;
#pragma unroll
    for (int ks = 0; ks < 4; ++ks) {
        const int kgA = 2*ks + (lane >> 4);
        const int kgB = 2*ks + ((lane >> 3) & 1);
        uint32_t aoff  = (uint32_t)arow*128u  + (uint32_t)((kgA ^ (arow  & 7)) << 4);
        uint32_t boff0 = (uint32_t)brow0*128u + (uint32_t)((kgB ^ (brow0 & 7)) << 4);
        uint32_t boff1 = (uint32_t)brow1*128u + (uint32_t)((kgB ^ (brow1 & 7)) << 4);
        uint32_t ah[4], al[4], bh0[4], bh1[4], bl0[4], bl1[4];
        ldsm_x4(ah,  sb + aHi + aoff);
        ldsm_x4(al,  sb + aLo + aoff);
        ldsm_x4(bh0, sb + bHi + boff0);
        ldsm_x4(bh1, sb + bHi + boff1);
        ldsm_x4(bl0, sb + bLo + boff0);
        ldsm_x4(bl1, sb + bLo + boff1);
#pragma unroll
        for (int j = 0; j < 4; ++j) {
            const uint32_t* bh = (j < 2) ? bh0 : bh1;
            const uint32_t* bl = (j < 2) ? bl0 : bl1;
            const int o = (j & 1) * 2;
            mma16816(S[j], ah, bh + o);
            mma16816(S[j], al, bh + o);
            mma16816(S[j], ah, bl + o);
        }
    }
}

__device__ __forceinline__ void gemm2_split(uint32_t sb, uint32_t pHi, uint32_t pLo,
                                            uint32_t vHi, uint32_t vLo,
                                            int m0, int n0, float O[4][4])
{
    const int lane = threadIdx.x & 31;
    const int arow = m0 + (lane & 15);
    const int g = lane >> 3, rr = lane & 7;
#pragma unroll
    for (int ks = 0; ks < 4; ++ks) {
        const int kgA = 2*ks + (lane >> 4);
        uint32_t aoff = (uint32_t)arow*128u + (uint32_t)((kgA ^ (arow & 7)) << 4);
        uint32_t ah[4], al[4];
        ldsm_x4(ah, sb + pHi + aoff);
        ldsm_x4(al, sb + pLo + aoff);
        const int s_row = ks*16 + ((g & 1) << 3) + rr;
        const uint32_t vrow = (uint32_t)s_row * 128u;
        const uint32_t sw = (uint32_t)(s_row & 7);
#pragma unroll
        for (int half = 0; half < 2; ++half) {
            const int h0 = n0 + half*16 + ((g >> 1) << 3);
            uint32_t voff = vrow + ((((uint32_t)h0 >> 3) ^ sw) << 4);
            uint32_t vh[4], vl[4];
            ldsm_x4_t(vh, sb + vHi + voff);
            ldsm_x4_t(vl, sb + vLo + voff);
#pragma unroll
            for (int jj = 0; jj < 2; ++jj) {
                const int j = half*2 + jj;
                mma16816(O[j], ah, vh + jj*2);
                mma16816(O[j], al, vh + jj*2);
                mma16816(O[j], ah, vl + jj*2);
            }
        }
    }
}

__device__ __forceinline__ void store_p(char* sm, int row, int col,
                                        float p0, float p1) {
    __nv_bfloat16 h0 = __float2bfloat16(p0), h1 = __float2bfloat16(p1);
    uint32_t hv = (uint32_t)__bfloat16_as_ushort(h0) |
                  ((uint32_t)__bfloat16_as_ushort(h1) << 16);
    uint32_t lv = pack_bf16(p0 - __bfloat162float(h0), p1 - __bfloat162float(h1));
    uint32_t g = (uint32_t)(col >> 3);
    uint32_t off = (uint32_t)row*128u + ((g ^ (uint32_t)(row & 7)) << 4)
                 + (uint32_t)((col & 7) * 2);
    *(uint32_t*)(sm + OPHI + off) = hv;
    *(uint32_t*)(sm + OPLO + off) = lv;
}

__global__ __launch_bounds__(256, 2) void attn_kernel()
{
    extern __shared__ char sm[];
    const uint32_t sb = smem_u32(sm);
    const int tid  = threadIdx.x;
    const int lane = tid & 31;
    const int wid  = tid >> 5;
    const int wr = wid & 3, wc = wid >> 2;
    const int m0 = wr * 16, n0 = wc * 32;
    const int bb = blockIdx.y;

    const int ti    = 63 - ((int)blockIdx.x >> 1);   // big tiles first (LPT)
    const int split = (int)blockIdx.x & 1;
    const int t0    = ti * 64;
    const int nblk  = ti + 1;
    const int halfb = (nblk + 1) >> 1;
    const int sBeg  = split ? halfb : 0;
    const int sEnd  = split ? nblk  : halfb;

    const __nv_bfloat16* Khi = g_Khi + (size_t)bb * T_ * HS_;
    const __nv_bfloat16* Klo = g_Klo + (size_t)bb * T_ * HS_;
    const __nv_bfloat16* Qhi = g_Qhi + (size_t)bb * T_ * HS_;
    const __nv_bfloat16* Qlo = g_Qlo + (size_t)bb * T_ * HS_;
    const __nv_bfloat16* Vhi = g_Vhi + (size_t)bb * T_ * HS_;
    const __nv_bfloat16* Vlo = g_Vlo + (size_t)bb * T_ * HS_;

    float Oa[4][4];
#pragma unroll
    for (int j = 0; j < 4; ++j)
#pragma unroll
        for (int q = 0; q < 4; ++q) Oa[j][q] = 0.f;
    float l0 = 0.f, l1 = 0.f;
    const int rr0 = t0 + m0 + (lane >> 2), rr1 = rr0 + 8;

    if (sBeg < sEnd) {
        ld_tile(sm, OKHI, Khi + (size_t)t0 * HS_);
        ld_tile(sm, OKLO, Klo + (size_t)t0 * HS_);
        ld_tile(sm, OBUF(0) +     0u, Qhi + (size_t)sBeg * 64 * HS_);
        ld_tile(sm, OBUF(0) +  8192u, Qlo + (size_t)sBeg * 64 * HS_);
        ld_tile(sm, OBUF(0) + 16384u, Vhi + (size_t)sBeg * 64 * HS_);
        ld_tile(sm, OBUF(0) + 24576u, Vlo + (size_t)sBeg * 64 * HS_);
        __syncthreads();

        for (int it = sBeg, j2 = 0; it < sEnd; ++it, ++j2) {
            const int s0 = it * 64;
            const uint32_t cb = OBUF(j2 & 1);
            const uint32_t nb = OBUF(1 - (j2 & 1));
            const bool hasNext = (it + 1 < sEnd);

            uint4 pf[8];
            if (hasNext) {
                const int sn = s0 + 64;
#pragma unroll
                for (int t4 = 0; t4 < 4; ++t4) {
                    const __nv_bfloat16* s4 =
                        (t4 == 0 ? Qhi : t4 == 1 ? Qlo : t4 == 2 ? Vhi : Vlo)
                        + (size_t)sn * HS_;
#pragma unroll
                    for (int i = 0; i < 2; ++i) {
                        int idx = tid + i * 256, r = idx >> 3, cc = idx & 7;
                        pf[t4*2 + i] = *(const uint4*)(s4 + (size_t)r * HS_ + cc * 8);
                    }
                }
            }

            float S[4][4];
#pragma unroll
            for (int j = 0; j < 4; ++j)
#pragma unroll
                for (int q = 0; q < 4; ++q) S[j][q] = 0.f;
            gemm_split(sb, OKHI, OKLO, cb, cb + 8192u, m0, n0, S);

            if (hasNext) {
#pragma unroll
                for (int t4 = 0; t4 < 4; ++t4) {
                    const uint32_t dst = nb + (uint32_t)t4 * 8192u;
#pragma unroll
                    for (int i = 0; i < 2; ++i) {
                        int idx = tid + i * 256, r = idx >> 3, cc = idx & 7;
                        uint32_t off = (uint32_t)r * 128u
                                     + (uint32_t)((cc ^ (r & 7)) << 4);
                        *(uint4*)(sm + dst + off) = pf[t4*2 + i];
                    }
                }
            }

            const bool diag = (it == nblk - 1);
#pragma unroll
            for (int j = 0; j < 4; ++j) {
                const int cl = n0 + 8*j + 2*(lane & 3);
                const int cg = s0 + cl;
                float p00 = __expf(S[j][0]);
                float p01 = __expf(S[j][1]);
                float p10 = __expf(S[j][2]);
                float p11 = __expf(S[j][3]);
                if (diag) {
                    if (cg     > rr0) p00 = 0.f;
                    if (cg + 1 > rr0) p01 = 0.f;
                    if (cg     > rr1) p10 = 0.f;
                    if (cg + 1 > rr1) p11 = 0.f;
                }
                l0 += p00 + p01;
                l1 += p10 + p11;
                store_p(sm, m0 + (lane >> 2),     cl, p00, p01);
                store_p(sm, m0 + (lane >> 2) + 8, cl, p10, p11);
            }
            __syncthreads();

            gemm2_split(sb, OPHI, OPLO, cb + 16384u, cb + 24576u, m0, n0, Oa);
            __syncthreads();
        }
    }

    // epilogue: write UNNORMALIZED partials (linear combine across splits)
    l0 += __shfl_xor_sync(0xffffffffu, l0, 1);
    l0 += __shfl_xor_sync(0xffffffffu, l0, 2);
    l1 += __shfl_xor_sync(0xffffffffu, l1, 1);
    l1 += __shfl_xor_sync(0xffffffffu, l1, 2);
    // l needs cross-wc combine: use smem scratch in K region (loop is done)
    __syncthreads();
    float* l_sm = (float*)(sm + OKHI);
    if ((lane & 3) == 0) {
        l_sm[wc*64 + m0 + (lane >> 2)]     = l0;
        l_sm[wc*64 + m0 + (lane >> 2) + 8] = l1;
    }
    __syncthreads();

    float* Op = g_Op[split] + ((size_t)bb * T_) * HS_;
    {
        const int rl = m0 + (lane >> 2);
        if (wc == 0 && (lane & 3) == 0) {
            g_lp[split][(size_t)bb * T_ + t0 + rl]     = l_sm[rl]     + l_sm[64 + rl];
            g_lp[split][(size_t)bb * T_ + t0 + rl + 8] = l_sm[rl + 8] + l_sm[64 + rl + 8];
        }
        float2* b0p = (float2*)(Op + (size_t)(t0 + rl)     * HS_);
        float2* b1p = (float2*)(Op + (size_t)(t0 + rl + 8) * HS_);
#pragma unroll
        for (int j = 0; j < 4; ++j) {
            const int c = n0 + 8*j + 2*(lane & 3);
            b0p[c >> 1] = make_float2(Oa[j][0], Oa[j][1]);
            b1p[c >> 1] = make_float2(Oa[j][2], Oa[j][3]);
        }
    }
}

// ===========================================================================
// Combine: out = (O0 + O1) / (l0 + l1)
// ===========================================================================
__global__ __launch_bounds__(256) void combine_kernel(float* __restrict__ out)
{
    const int idx = blockIdx.x * 256 + threadIdx.x;   // float4 index
    const int row = idx >> 4;                          // 16 float4 per row
    const float inv = 1.f / (g_lp[0][row] + g_lp[1][row]);
    float4 a = ((const float4*)g_Op[0])[idx];
    float4 b = ((const float4*)g_Op[1])[idx];
    float4 r;
    r.x = (a.x + b.x) * inv;
    r.y = (a.y + b.y) * inv;
    r.z = (a.z + b.z) * inv;
    r.w = (a.w + b.w) * inv;
    ((float4*)out)[idx] = r;
}

// ---------------------------------------------------------------------------
extern "C" void kernel_launch(void* const* d_in, const int* in_sizes, int n_in,
                              void* d_out, int out_size)
{
    (void)in_sizes; (void)n_in; (void)out_size;
    const float* x  = (const float*)d_in[0];
    const float* Wk = (const float*)d_in[1];
    const float* bk = (const float*)d_in[2];
    const float* Wq = (const float*)d_in[3];
    const float* bq = (const float*)d_in[4];
    const float* Wv = (const float*)d_in[5];
    const float* bv = (const float*)d_in[6];
    float* out = (float*)d_out;

    cudaFuncSetAttribute(proj_kernel,
                         cudaFuncAttributeMaxDynamicSharedMemorySize, PROJ_SMEM);
    cudaFuncSetAttribute(attn_kernel,
                         cudaFuncAttributeMaxDynamicSharedMemorySize, ATTN_SMEM);

    wconv_kernel<<<192, 256>>>(Wk, Wq, Wv);
    proj_kernel<<<BT_/128, 256, PROJ_SMEM>>>(x, bk, bq, bv);
    attn_kernel<<<dim3(128, B_), 256, ATTN_SMEM>>>();
    combine_kernel<<<BT_*HS_/4/256, 256>>>(out);
}

// round 14
// speedup vs baseline: 1.7291x; 1.7291x over previous
#include <cuda_runtime.h>
#include <cuda_bf16.h>
#include <cstdint>
#include <math_constants.h>

#define B_   4
#define T_   4096
#define EMB_ 768
#define HS_  64
#define BT_  (B_*T_)

// bf16 split operands. K/Q/V natural [row][h]; W converted to [k][n0..191].
__device__ __nv_bfloat16 g_Khi[BT_*HS_];
__device__ __nv_bfloat16 g_Klo[BT_*HS_];
__device__ __nv_bfloat16 g_Qhi[BT_*HS_];
__device__ __nv_bfloat16 g_Qlo[BT_*HS_];
__device__ __nv_bfloat16 g_Vhi[BT_*HS_];
__device__ __nv_bfloat16 g_Vlo[BT_*HS_];
__device__ __nv_bfloat16 g_Whi[EMB_*192];
__device__ __nv_bfloat16 g_Wlo[EMB_*192];

__device__ __forceinline__ uint32_t smem_u32(const void* p) {
    uint32_t a;
    asm("{ .reg .u64 t; cvta.to.shared.u64 t, %1; cvt.u32.u64 %0, t; }"
        : "=r"(a) : "l"(p));
    return a;
}
__device__ __forceinline__ void ldsm_x4(uint32_t* r, uint32_t addr) {
    asm volatile("ldmatrix.sync.aligned.m8n8.x4.shared.b16 {%0,%1,%2,%3}, [%4];"
        : "=r"(r[0]), "=r"(r[1]), "=r"(r[2]), "=r"(r[3]) : "r"(addr));
}
__device__ __forceinline__ void ldsm_x4_t(uint32_t* r, uint32_t addr) {
    asm volatile("ldmatrix.sync.aligned.m8n8.x4.trans.shared.b16 {%0,%1,%2,%3}, [%4];"
        : "=r"(r[0]), "=r"(r[1]), "=r"(r[2]), "=r"(r[3]) : "r"(addr));
}
__device__ __forceinline__ void mma16816(float* d, const uint32_t* a, const uint32_t* b) {
    asm volatile("mma.sync.aligned.m16n8k16.row.col.f32.bf16.bf16.f32 "
        "{%0,%1,%2,%3},{%4,%5,%6,%7},{%8,%9},{%0,%1,%2,%3};"
        : "+f"(d[0]), "+f"(d[1]), "+f"(d[2]), "+f"(d[3])
        : "r"(a[0]), "r"(a[1]), "r"(a[2]), "r"(a[3]), "r"(b[0]), "r"(b[1]));
}
__device__ __forceinline__ uint32_t pack_bf16(float a, float b) {
    return (uint32_t)__bfloat16_as_ushort(__float2bfloat16(a)) |
           ((uint32_t)__bfloat16_as_ushort(__float2bfloat16(b)) << 16);
}
#define CP_ASYNC16(dst, src) \
    asm volatile("cp.async.cg.shared.global [%0], [%1], 16;" \
        :: "r"(dst), "l"(src) : "memory")
#define CP_COMMIT()  asm volatile("cp.async.commit_group;" ::: "memory")
#define CP_WAIT0()   asm volatile("cp.async.wait_group 0;" ::: "memory")

// ===========================================================================
// W converter: fp32 [768x64] x3 -> bf16 hi/lo [768][192] (k-major rows).
// ===========================================================================
__global__ __launch_bounds__(256) void wconv_kernel(
    const float* __restrict__ Wk, const float* __restrict__ Wq,
    const float* __restrict__ Wv)
{
    const int e = blockIdx.x * 256 + threadIdx.x;
    const int k = e >> 6, n = e & 63;
#pragma unroll
    for (int mat = 0; mat < 3; ++mat) {
        const float* src = (mat == 0) ? Wk : (mat == 1) ? Wq : Wv;
        float v = src[e];
        __nv_bfloat16 h = __float2bfloat16(v);
        size_t o = (size_t)k * 192 + mat * 64 + n;
        g_Whi[o] = h;
        g_Wlo[o] = __float2bfloat16(v - __bfloat162float(h));
    }
}

// ===========================================================================
// Tensorized projection, software-pipelined:
// x double-buffered (LDG regs -> convert -> STS), W double-buffered (cp.async).
// smem: X[2] 32KB each @0/32768 | W[2] 48KB each @65536/114688 -> 160KB.
// ===========================================================================
#define PXB(b) ((uint32_t)(b) * 32768u)            // hi +0 (16K), lo +16384
#define PWB(b) (65536u + (uint32_t)(b) * 49152u)   // mat*16384 + hl*8192
#define PROJ_SMEM 163840u

__device__ __forceinline__ void proj_w_cpasync(uint32_t sbuf, int kc, int tid) {
#pragma unroll
    for (int hl = 0; hl < 2; ++hl) {
        const __nv_bfloat16* gw = hl ? g_Wlo : g_Whi;
#pragma unroll
        for (int i = 0; i < 6; ++i) {
            int idx = tid + i * 256;
            int k = idx / 24, nc = (idx % 24) * 8;
            const __nv_bfloat16* src = gw + (size_t)(kc*64 + k) * 192 + nc;
            int mat = nc >> 6, ln = nc & 63;
            uint32_t dst = sbuf + (uint32_t)mat*16384u + (uint32_t)hl*8192u
                         + (uint32_t)k*128u
                         + (uint32_t)((((ln >> 3) ^ (k & 7))) << 4);
            CP_ASYNC16(dst, src);
        }
    }
    CP_COMMIT();
}

__device__ __forceinline__ void proj_x_sts(char* sm, uint32_t xbuf,
                                           const float4* pf, int tid) {
#pragma unroll
    for (int i = 0; i < 8; ++i) {
        int idx = tid + i * 256;
        int r = idx >> 4, c4 = (idx & 15) * 4;
        float4 v = pf[i];
        __nv_bfloat16 hx = __float2bfloat16(v.x), hy = __float2bfloat16(v.y);
        __nv_bfloat16 hz = __float2bfloat16(v.z), hw = __float2bfloat16(v.w);
        uint32_t h01 = (uint32_t)__bfloat16_as_ushort(hx) |
                       ((uint32_t)__bfloat16_as_ushort(hy) << 16);
        uint32_t h23 = (uint32_t)__bfloat16_as_ushort(hz) |
                       ((uint32_t)__bfloat16_as_ushort(hw) << 16);
        uint32_t l01 = pack_bf16(v.x - __bfloat162float(hx),
                                 v.y - __bfloat162float(hy));
        uint32_t l23 = pack_bf16(v.z - __bfloat162float(hz),
                                 v.w - __bfloat162float(hw));
        uint32_t off = (uint32_t)r * 128u
                     + (uint32_t)((((c4 >> 3) ^ (r & 7))) << 4)
                     + (uint32_t)((c4 & 7) * 2);
        *(uint2*)(sm + xbuf + off) = make_uint2(h01, h23);
        *(uint2*)(sm + xbuf + 16384u + off) = make_uint2(l01, l23);
    }
}

__global__ __launch_bounds__(256) void proj_kernel(
    const float* __restrict__ x,
    const float* __restrict__ bk, const float* __restrict__ bq,
    const float* __restrict__ bv)
{
    extern __shared__ char sm[];
    const uint32_t sb = smem_u32(sm);
    const int tid = threadIdx.x, lane = tid & 31, wid = tid >> 5;
    const int m0 = (wid & 3) * 32, n0 = (wid >> 2) * 96;
    const int row0 = blockIdx.x * 128;

    float acc[2][12][4];
#pragma unroll
    for (int a = 0; a < 2; ++a)
#pragma unroll
        for (int b = 0; b < 12; ++b)
#pragma unroll
            for (int c = 0; c < 4; ++c) acc[a][b][c] = 0.f;

    // prologue: stage 0 into buffer 0
    {
        proj_w_cpasync(sb + PWB(0), 0, tid);
        float4 pf[8];
#pragma unroll
        for (int i = 0; i < 8; ++i) {
            int idx = tid + i * 256;
            int r = idx >> 4, c4 = (idx & 15) * 4;
            pf[i] = *(const float4*)(x + (size_t)(row0 + r) * EMB_ + c4);
        }
        proj_x_sts(sm, PXB(0), pf, tid);
        CP_WAIT0();
    }
    __syncthreads();

    for (int kc = 0; kc < 12; ++kc) {
        const int b = kc & 1;
        const bool more = (kc + 1 < 12);

        float4 pf[8];
        if (more) {
            // issue next-stage loads early (hidden under MMAs)
#pragma unroll
            for (int i = 0; i < 8; ++i) {
                int idx = tid + i * 256;
                int r = idx >> 4, c4 = (idx & 15) * 4;
                pf[i] = *(const float4*)(x + (size_t)(row0 + r) * EMB_
                                           + (kc + 1) * 64 + c4);
            }
            proj_w_cpasync(sb + PWB(1 - b), kc + 1, tid);
        }

        // MMA on stage kc (buffer b)
        const uint32_t xb = PXB(b), wb = PWB(b);
#pragma unroll
        for (int ks = 0; ks < 4; ++ks) {
            uint32_t ah[2][4], al[2][4];
#pragma unroll
            for (int mt = 0; mt < 2; ++mt) {
                int arow = m0 + mt*16 + (lane & 15);
                int kg = 2*ks + (lane >> 4);
                uint32_t aoff = (uint32_t)arow*128u
                              + (uint32_t)(((kg ^ (arow & 7))) << 4);
                ldsm_x4(ah[mt], sb + xb + aoff);
                ldsm_x4(al[mt], sb + xb + 16384u + aoff);
            }
            const int g = lane >> 3, rr = lane & 7;
            const int krow = ks*16 + ((g & 1) << 3) + rr;
#pragma unroll
            for (int grp = 0; grp < 6; ++grp) {
                int hglob = n0 + grp*16 + ((g >> 1) << 3);
                int mat = hglob >> 6, lc = hglob & 63;
                uint32_t base = wb + (uint32_t)mat * 16384u;
                uint32_t voff = (uint32_t)krow*128u
                              + (uint32_t)((((lc >> 3) ^ (krow & 7))) << 4);
                uint32_t wh[4], wl[4];
                ldsm_x4_t(wh, sb + base + voff);
                ldsm_x4_t(wl, sb + base + 8192u + voff);
#pragma unroll
                for (int mt = 0; mt < 2; ++mt)
#pragma unroll
                    for (int jj = 0; jj < 2; ++jj) {
                        float* d = acc[mt][grp*2 + jj];
                        mma16816(d, ah[mt], wh + jj*2);
                        mma16816(d, al[mt], wh + jj*2);
                        mma16816(d, ah[mt], wl + jj*2);
                    }
            }
        }

        if (more) {
            proj_x_sts(sm, PXB(1 - b), pf, tid);
            CP_WAIT0();
        }
        __syncthreads();
    }

    // epilogue: bias, bf16 hi/lo split, stores
#pragma unroll
    for (int nj = 0; nj < 12; ++nj) {
        const int c0 = n0 + nj*8 + 2*(lane & 3);
        const int mat = c0 >> 6, lc = c0 & 63;
        const float* bp = (mat == 0) ? bk : (mat == 1) ? bq : bv;
        const float b0 = bp[lc], b1 = bp[lc + 1];
        __nv_bfloat16* hp = (mat == 0) ? g_Khi : (mat == 1) ? g_Qhi : g_Vhi;
        __nv_bfloat16* lp = (mat == 0) ? g_Klo : (mat == 1) ? g_Qlo : g_Vlo;
#pragma unroll
        for (int mt = 0; mt < 2; ++mt)
#pragma unroll
            for (int h = 0; h < 2; ++h) {
                const int r = row0 + m0 + mt*16 + (lane >> 2) + h*8;
                float v0 = acc[mt][nj][h*2 + 0] + b0;
                float v1 = acc[mt][nj][h*2 + 1] + b1;
                __nv_bfloat16 h0 = __float2bfloat16(v0);
                __nv_bfloat16 h1 = __float2bfloat16(v1);
                uint32_t hv = (uint32_t)__bfloat16_as_ushort(h0) |
                              ((uint32_t)__bfloat16_as_ushort(h1) << 16);
                uint32_t lv = pack_bf16(v0 - __bfloat162float(h0),
                                        v1 - __bfloat162float(h1));
                size_t o = (size_t)r * HS_ + lc;
                *(uint32_t*)(hp + o) = hv;
                *(uint32_t*)(lp + o) = lv;
            }
    }
}

// ===========================================================================
// Attention: R9 structure exactly (256 thr, m16n32/warp, 2-pass pairing,
// 1 CTA/SM), prefetch switched to cp.async.
// ===========================================================================
#define OKHI  0u
#define OKLO  8192u
#define OBUF(b) (16384u + (uint32_t)(b) * 32768u)
#define OPHI  81920u
#define OPLO  90112u
#define ATTN_SMEM 98304u

__device__ __forceinline__ void ld_tile(char* sm, uint32_t dst,
                                        const __nv_bfloat16* __restrict__ src) {
#pragma unroll
    for (int i = 0; i < 2; ++i) {
        int idx = threadIdx.x + i * 256;
        int r = idx >> 3, cc = idx & 7;
        uint32_t off = (uint32_t)r * 128u + (uint32_t)((cc ^ (r & 7)) << 4);
        *(uint4*)(sm + dst + off) = *(const uint4*)(src + (size_t)r * HS_ + cc * 8);
    }
}

__device__ __forceinline__ void gemm_split(uint32_t sb, uint32_t aHi, uint32_t aLo,
                                           uint32_t bHi, uint32_t bLo,
                                           int m0, int n0, float S[4][4])
{
    const int lane = threadIdx.x & 31;
    const int arow  = m0 + (lane & 15);
    const int brow0 = n0 + (lane & 7) + ((lane >> 4) << 3);
    const int brow1 = brow0 + 16;
#pragma unroll
    for (int ks = 0; ks < 4; ++ks) {
        const int kgA = 2*ks + (lane >> 4);
        const int kgB = 2*ks + ((lane >> 3) & 1);
        uint32_t aoff  = (uint32_t)arow*128u  + (uint32_t)((kgA ^ (arow  & 7)) << 4);
        uint32_t boff0 = (uint32_t)brow0*128u + (uint32_t)((kgB ^ (brow0 & 7)) << 4);
        uint32_t boff1 = (uint32_t)brow1*128u + (uint32_t)((kgB ^ (brow1 & 7)) << 4);
        uint32_t ah[4], al[4], bh0[4], bh1[4], bl0[4], bl1[4];
        ldsm_x4(ah,  sb + aHi + aoff);
        ldsm_x4(al,  sb + aLo + aoff);
        ldsm_x4(bh0, sb + bHi + boff0);
        ldsm_x4(bh1, sb + bHi + boff1);
        ldsm_x4(bl0, sb + bLo + boff0);
        ldsm_x4(bl1, sb + bLo + boff1);
#pragma unroll
        for (int j = 0; j < 4; ++j) {
            const uint32_t* bh = (j < 2) ? bh0 : bh1;
            const uint32_t* bl = (j < 2) ? bl0 : bl1;
            const int o = (j & 1) * 2;
            mma16816(S[j], ah, bh + o);
            mma16816(S[j], al, bh + o);
            mma16816(S[j], ah, bl + o);
        }
    }
}

__device__ __forceinline__ void gemm2_split(uint32_t sb, uint32_t pHi, uint32_t pLo,
                                            uint32_t vHi, uint32_t vLo,
                                            int m0, int n0, float O[4][4])
{
    const int lane = threadIdx.x & 31;
    const int arow = m0 + (lane & 15);
    const int g = lane >> 3, rr = lane & 7;
#pragma unroll
    for (int ks = 0; ks < 4; ++ks) {
        const int kgA = 2*ks + (lane >> 4);
        uint32_t aoff = (uint32_t)arow*128u + (uint32_t)((kgA ^ (arow & 7)) << 4);
        uint32_t ah[4], al[4];
        ldsm_x4(ah, sb + pHi + aoff);
        ldsm_x4(al, sb + pLo + aoff);
        const int s_row = ks*16 + ((g & 1) << 3) + rr;
        const uint32_t vrow = (uint32_t)s_row * 128u;
        const uint32_t sw = (uint32_t)(s_row & 7);
#pragma unroll
        for (int half = 0; half < 2; ++half) {
            const int h0 = n0 + half*16 + ((g >> 1) << 3);
            uint32_t voff = vrow + ((((uint32_t)h0 >> 3) ^ sw) << 4);
            uint32_t vh[4], vl[4];
            ldsm_x4_t(vh, sb + vHi + voff);
            ldsm_x4_t(vl, sb + vLo + voff);
#pragma unroll
            for (int jj = 0; jj < 2; ++jj) {
                const int j = half*2 + jj;
                mma16816(O[j], ah, vh + jj*2);
                mma16816(O[j], al, vh + jj*2);
                mma16816(O[j], ah, vl + jj*2);
            }
        }
    }
}

__device__ __forceinline__ void store_p(char* sm, int row, int col,
                                        float p0, float p1) {
    __nv_bfloat16 h0 = __float2bfloat16(p0), h1 = __float2bfloat16(p1);
    uint32_t hv = (uint32_t)__bfloat16_as_ushort(h0) |
                  ((uint32_t)__bfloat16_as_ushort(h1) << 16);
    uint32_t lv = pack_bf16(p0 - __bfloat162float(h0), p1 - __bfloat162float(h1));
    uint32_t g = (uint32_t)(col >> 3);
    uint32_t off = (uint32_t)row*128u + ((g ^ (uint32_t)(row & 7)) << 4)
                 + (uint32_t)((col & 7) * 2);
    *(uint32_t*)(sm + OPHI + off) = hv;
    *(uint32_t*)(sm + OPLO + off) = lv;
}

__global__ __launch_bounds__(256) void attn_kernel(float* __restrict__ out)
{
    extern __shared__ char sm[];
    const uint32_t sb = smem_u32(sm);
    const int tid  = threadIdx.x;
    const int lane = tid & 31;
    const int wid  = tid >> 5;
    const int wr = wid & 3, wc = wid >> 2;
    const int m0 = wr * 16, n0 = wc * 32;
    const int bb = blockIdx.y;

    const __nv_bfloat16* Khi = g_Khi + (size_t)bb * T_ * HS_;
    const __nv_bfloat16* Klo = g_Klo + (size_t)bb * T_ * HS_;
    const __nv_bfloat16* Qhi = g_Qhi + (size_t)bb * T_ * HS_;
    const __nv_bfloat16* Qlo = g_Qlo + (size_t)bb * T_ * HS_;
    const __nv_bfloat16* Vhi = g_Vhi + (size_t)bb * T_ * HS_;
    const __nv_bfloat16* Vlo = g_Vlo + (size_t)bb * T_ * HS_;

    for (int pass = 0; pass < 2; ++pass) {
        const int ti = pass ? 63 - (int)blockIdx.x : (int)blockIdx.x;
        const int t0 = ti * 64;

        __syncthreads();
        ld_tile(sm, OKHI, Khi + (size_t)t0 * HS_);
        ld_tile(sm, OKLO, Klo + (size_t)t0 * HS_);
        ld_tile(sm, OBUF(0) +     0u, Qhi);
        ld_tile(sm, OBUF(0) +  8192u, Qlo);
        ld_tile(sm, OBUF(0) + 16384u, Vhi);
        ld_tile(sm, OBUF(0) + 24576u, Vlo);

        float Oa[4][4];
#pragma unroll
        for (int j = 0; j < 4; ++j)
#pragma unroll
            for (int q = 0; q < 4; ++q) Oa[j][q] = 0.f;
        float l0 = 0.f, l1 = 0.f;
        const int rr0 = t0 + m0 + (lane >> 2), rr1 = rr0 + 8;

        __syncthreads();

        for (int s0 = 0, it = 0; s0 <= t0; s0 += 64, ++it) {
            const uint32_t cb = OBUF(it & 1);
            const uint32_t nb = OBUF(1 - (it & 1));
            const int sn = s0 + 64;
            const bool hasNext = (sn <= t0);

            // cp.async next tiles into the idle buffer (register-free)
            if (hasNext) {
#pragma unroll
                for (int t4 = 0; t4 < 4; ++t4) {
                    const __nv_bfloat16* s4 =
                        (t4 == 0 ? Qhi : t4 == 1 ? Qlo : t4 == 2 ? Vhi : Vlo)
                        + (size_t)sn * HS_;
                    const uint32_t db = sb + nb + (uint32_t)t4 * 8192u;
#pragma unroll
                    for (int i = 0; i < 2; ++i) {
                        int idx = tid + i * 256, r = idx >> 3, cc = idx & 7;
                        uint32_t off = (uint32_t)r * 128u
                                     + (uint32_t)((cc ^ (r & 7)) << 4);
                        CP_ASYNC16(db + off, s4 + (size_t)r * HS_ + cc * 8);
                    }
                }
                CP_COMMIT();
            }

            float S[4][4];
#pragma unroll
            for (int j = 0; j < 4; ++j)
#pragma unroll
                for (int q = 0; q < 4; ++q) S[j][q] = 0.f;
            gemm_split(sb, OKHI, OKLO, cb, cb + 8192u, m0, n0, S);

            const bool diag = (s0 == t0);
#pragma unroll
            for (int j = 0; j < 4; ++j) {
                const int cl = n0 + 8*j + 2*(lane & 3);
                const int cg = s0 + cl;
                float p00 = __expf(S[j][0]);
                float p01 = __expf(S[j][1]);
                float p10 = __expf(S[j][2]);
                float p11 = __expf(S[j][3]);
                if (diag) {
                    if (cg     > rr0) p00 = 0.f;
                    if (cg + 1 > rr0) p01 = 0.f;
                    if (cg     > rr1) p10 = 0.f;
                    if (cg + 1 > rr1) p11 = 0.f;
                }
                l0 += p00 + p01;
                l1 += p10 + p11;
                store_p(sm, m0 + (lane >> 2),     cl, p00, p01);
                store_p(sm, m0 + (lane >> 2) + 8, cl, p10, p11);
            }
            __syncthreads();                   // P visible across wc halves

            gemm2_split(sb, OPHI, OPLO, cb + 16384u, cb + 24576u, m0, n0, Oa);

            if (hasNext) CP_WAIT0();
            __syncthreads();                   // buffers reusable
        }

        // epilogue: reduce l across lanes + wc warps, scale, store
        float* l_sm = (float*)(sm + OKHI);
        l0 += __shfl_xor_sync(0xffffffffu, l0, 1);
        l0 += __shfl_xor_sync(0xffffffffu, l0, 2);
        l1 += __shfl_xor_sync(0xffffffffu, l1, 1);
        l1 += __shfl_xor_sync(0xffffffffu, l1, 2);
        if ((lane & 3) == 0) {
            l_sm[wc*64 + m0 + (lane >> 2)]     = l0;
            l_sm[wc*64 + m0 + (lane >> 2) + 8] = l1;
        }
        __syncthreads();
        {
            const int rl = m0 + (lane >> 2);
            const float inv0 = 1.f / (l_sm[rl]     + l_sm[64 + rl]);
            const float inv1 = 1.f / (l_sm[rl + 8] + l_sm[64 + rl + 8]);
            float2* b0p = (float2*)(out + ((size_t)bb * T_ + t0 + rl)     * HS_);
            float2* b1p = (float2*)(out + ((size_t)bb * T_ + t0 + rl + 8) * HS_);
#pragma unroll
            for (int j = 0; j < 4; ++j) {
                const int c = n0 + 8*j + 2*(lane & 3);
                b0p[c >> 1] = make_float2(Oa[j][0]*inv0, Oa[j][1]*inv0);
                b1p[c >> 1] = make_float2(Oa[j][2]*inv1, Oa[j][3]*inv1);
            }
        }
    }
}

// ---------------------------------------------------------------------------
extern "C" void kernel_launch(void* const* d_in, const int* in_sizes, int n_in,
                              void* d_out, int out_size)
{
    (void)in_sizes; (void)n_in; (void)out_size;
    const float* x  = (const float*)d_in[0];
    const float* Wk = (const float*)d_in[1];
    const float* bk = (const float*)d_in[2];
    const float* Wq = (const float*)d_in[3];
    const float* bq = (const float*)d_in[4];
    const float* Wv = (const float*)d_in[5];
    const float* bv = (const float*)d_in[6];
    float* out = (float*)d_out;

    cudaFuncSetAttribute(proj_kernel,
                         cudaFuncAttributeMaxDynamicSharedMemorySize, PROJ_SMEM);
    cudaFuncSetAttribute(attn_kernel,
                         cudaFuncAttributeMaxDynamicSharedMemorySize, ATTN_SMEM);

    wconv_kernel<<<192, 256>>>(Wk, Wq, Wv);
    proj_kernel<<<BT_/128, 256, PROJ_SMEM>>>(x, bk, bq, bv);
    attn_kernel<<<dim3(32, B_), 256, ATTN_SMEM>>>(out);
}

// round 17
// speedup vs baseline: 1.8230x; 1.0543x over previous
#include <cuda_runtime.h>
#include <cuda_bf16.h>
#include <cstdint>
#include <math_constants.h>

#define B_   4
#define T_   4096
#define EMB_ 768
#define HS_  64
#define BT_  (B_*T_)

// bf16 split operands. K/Q/V natural [row][h]; W converted to [k][n0..191].
__device__ __nv_bfloat16 g_Khi[BT_*HS_];
__device__ __nv_bfloat16 g_Klo[BT_*HS_];
__device__ __nv_bfloat16 g_Qhi[BT_*HS_];
__device__ __nv_bfloat16 g_Qlo[BT_*HS_];
__device__ __nv_bfloat16 g_Vhi[BT_*HS_];
__device__ __nv_bfloat16 g_Vlo[BT_*HS_];
__device__ __nv_bfloat16 g_Whi[EMB_*192];
__device__ __nv_bfloat16 g_Wlo[EMB_*192];

__device__ __forceinline__ uint32_t smem_u32(const void* p) {
    uint32_t a;
    asm("{ .reg .u64 t; cvta.to.shared.u64 t, %1; cvt.u32.u64 %0, t; }"
        : "=r"(a) : "l"(p));
    return a;
}
__device__ __forceinline__ void ldsm_x4(uint32_t* r, uint32_t addr) {
    asm volatile("ldmatrix.sync.aligned.m8n8.x4.shared.b16 {%0,%1,%2,%3}, [%4];"
        : "=r"(r[0]), "=r"(r[1]), "=r"(r[2]), "=r"(r[3]) : "r"(addr));
}
__device__ __forceinline__ void ldsm_x4_t(uint32_t* r, uint32_t addr) {
    asm volatile("ldmatrix.sync.aligned.m8n8.x4.trans.shared.b16 {%0,%1,%2,%3}, [%4];"
        : "=r"(r[0]), "=r"(r[1]), "=r"(r[2]), "=r"(r[3]) : "r"(addr));
}
__device__ __forceinline__ void mma16816(float* d, const uint32_t* a, const uint32_t* b) {
    asm volatile("mma.sync.aligned.m16n8k16.row.col.f32.bf16.bf16.f32 "
        "{%0,%1,%2,%3},{%4,%5,%6,%7},{%8,%9},{%0,%1,%2,%3};"
        : "+f"(d[0]), "+f"(d[1]), "+f"(d[2]), "+f"(d[3])
        : "r"(a[0]), "r"(a[1]), "r"(a[2]), "r"(a[3]), "r"(b[0]), "r"(b[1]));
}
__device__ __forceinline__ uint32_t pack_bf16(float a, float b) {
    return (uint32_t)__bfloat16_as_ushort(__float2bfloat16(a)) |
           ((uint32_t)__bfloat16_as_ushort(__float2bfloat16(b)) << 16);
}
#define CP_ASYNC16(dst, src) \
    asm volatile("cp.async.cg.shared.global [%0], [%1], 16;" \
        :: "r"(dst), "l"(src) : "memory")
#define CP_COMMIT()  asm volatile("cp.async.commit_group;" ::: "memory")
#define CP_WAIT0()   asm volatile("cp.async.wait_group 0;" ::: "memory")

// ===========================================================================
// W converter: fp32 [768x64] x3 -> bf16 hi/lo [768][192] (k-major rows).
// ===========================================================================
__global__ __launch_bounds__(256) void wconv_kernel(
    const float* __restrict__ Wk, const float* __restrict__ Wq,
    const float* __restrict__ Wv)
{
    const int e = blockIdx.x * 256 + threadIdx.x;
    const int k = e >> 6, n = e & 63;
#pragma unroll
    for (int mat = 0; mat < 3; ++mat) {
        const float* src = (mat == 0) ? Wk : (mat == 1) ? Wq : Wv;
        float v = src[e];
        __nv_bfloat16 h = __float2bfloat16(v);
        size_t o = (size_t)k * 192 + mat * 64 + n;
        g_Whi[o] = h;
        g_Wlo[o] = __float2bfloat16(v - __bfloat162float(h));
    }
}

// ===========================================================================
// Tensorized projection, software-pipelined (unchanged from R14 pass).
// ===========================================================================
#define PXB(b) ((uint32_t)(b) * 32768u)
#define PWB(b) (65536u + (uint32_t)(b) * 49152u)
#define PROJ_SMEM 163840u

__device__ __forceinline__ void proj_w_cpasync(uint32_t sbuf, int kc, int tid) {
#pragma unroll
    for (int hl = 0; hl < 2; ++hl) {
        const __nv_bfloat16* gw = hl ? g_Wlo : g_Whi;
#pragma unroll
        for (int i = 0; i < 6; ++i) {
            int idx = tid + i * 256;
            int k = idx / 24, nc = (idx % 24) * 8;
            const __nv_bfloat16* src = gw + (size_t)(kc*64 + k) * 192 + nc;
            int mat = nc >> 6, ln = nc & 63;
            uint32_t dst = sbuf + (uint32_t)mat*16384u + (uint32_t)hl*8192u
                         + (uint32_t)k*128u
                         + (uint32_t)((((ln >> 3) ^ (k & 7))) << 4);
            CP_ASYNC16(dst, src);
        }
    }
    CP_COMMIT();
}

__device__ __forceinline__ void proj_x_sts(char* sm, uint32_t xbuf,
                                           const float4* pf, int tid) {
#pragma unroll
    for (int i = 0; i < 8; ++i) {
        int idx = tid + i * 256;
        int r = idx >> 4, c4 = (idx & 15) * 4;
        float4 v = pf[i];
        __nv_bfloat16 hx = __float2bfloat16(v.x), hy = __float2bfloat16(v.y);
        __nv_bfloat16 hz = __float2bfloat16(v.z), hw = __float2bfloat16(v.w);
        uint32_t h01 = (uint32_t)__bfloat16_as_ushort(hx) |
                       ((uint32_t)__bfloat16_as_ushort(hy) << 16);
        uint32_t h23 = (uint32_t)__bfloat16_as_ushort(hz) |
                       ((uint32_t)__bfloat16_as_ushort(hw) << 16);
        uint32_t l01 = pack_bf16(v.x - __bfloat162float(hx),
                                 v.y - __bfloat162float(hy));
        uint32_t l23 = pack_bf16(v.z - __bfloat162float(hz),
                                 v.w - __bfloat162float(hw));
        uint32_t off = (uint32_t)r * 128u
                     + (uint32_t)((((c4 >> 3) ^ (r & 7))) << 4)
                     + (uint32_t)((c4 & 7) * 2);
        *(uint2*)(sm + xbuf + off) = make_uint2(h01, h23);
        *(uint2*)(sm + xbuf + 16384u + off) = make_uint2(l01, l23);
    }
}

__global__ __launch_bounds__(256) void proj_kernel(
    const float* __restrict__ x,
    const float* __restrict__ bk, const float* __restrict__ bq,
    const float* __restrict__ bv)
{
    extern __shared__ char sm[];
    const uint32_t sb = smem_u32(sm);
    const int tid = threadIdx.x, lane = tid & 31, wid = tid >> 5;
    const int m0 = (wid & 3) * 32, n0 = (wid >> 2) * 96;
    const int row0 = blockIdx.x * 128;

    float acc[2][12][4];
#pragma unroll
    for (int a = 0; a < 2; ++a)
#pragma unroll
        for (int b = 0; b < 12; ++b)
#pragma unroll
            for (int c = 0; c < 4; ++c) acc[a][b][c] = 0.f;

    {
        proj_w_cpasync(sb + PWB(0), 0, tid);
        float4 pf[8];
#pragma unroll
        for (int i = 0; i < 8; ++i) {
            int idx = tid + i * 256;
            int r = idx >> 4, c4 = (idx & 15) * 4;
            pf[i] = *(const float4*)(x + (size_t)(row0 + r) * EMB_ + c4);
        }
        proj_x_sts(sm, PXB(0), pf, tid);
        CP_WAIT0();
    }
    __syncthreads();

    for (int kc = 0; kc < 12; ++kc) {
        const int b = kc & 1;
        const bool more = (kc + 1 < 12);

        float4 pf[8];
        if (more) {
#pragma unroll
            for (int i = 0; i < 8; ++i) {
                int idx = tid + i * 256;
                int r = idx >> 4, c4 = (idx & 15) * 4;
                pf[i] = *(const float4*)(x + (size_t)(row0 + r) * EMB_
                                           + (kc + 1) * 64 + c4);
            }
            proj_w_cpasync(sb + PWB(1 - b), kc + 1, tid);
        }

        const uint32_t xb = PXB(b), wb = PWB(b);
#pragma unroll
        for (int ks = 0; ks < 4; ++ks) {
            uint32_t ah[2][4], al[2][4];
#pragma unroll
            for (int mt = 0; mt < 2; ++mt) {
                int arow = m0 + mt*16 + (lane & 15);
                int kg = 2*ks + (lane >> 4);
                uint32_t aoff = (uint32_t)arow*128u
                              + (uint32_t)(((kg ^ (arow & 7))) << 4);
                ldsm_x4(ah[mt], sb + xb + aoff);
                ldsm_x4(al[mt], sb + xb + 16384u + aoff);
            }
            const int g = lane >> 3, rr = lane & 7;
            const int krow = ks*16 + ((g & 1) << 3) + rr;
#pragma unroll
            for (int grp = 0; grp < 6; ++grp) {
                int hglob = n0 + grp*16 + ((g >> 1) << 3);
                int mat = hglob >> 6, lc = hglob & 63;
                uint32_t base = wb + (uint32_t)mat * 16384u;
                uint32_t voff = (uint32_t)krow*128u
                              + (uint32_t)((((lc >> 3) ^ (krow & 7))) << 4);
                uint32_t wh[4], wl[4];
                ldsm_x4_t(wh, sb + base + voff);
                ldsm_x4_t(wl, sb + base + 8192u + voff);
#pragma unroll
                for (int mt = 0; mt < 2; ++mt)
#pragma unroll
                    for (int jj = 0; jj < 2; ++jj) {
                        float* d = acc[mt][grp*2 + jj];
                        mma16816(d, ah[mt], wh + jj*2);
                        mma16816(d, al[mt], wh + jj*2);
                        mma16816(d, ah[mt], wl + jj*2);
                    }
            }
        }

        if (more) {
            proj_x_sts(sm, PXB(1 - b), pf, tid);
            CP_WAIT0();
        }
        __syncthreads();
    }

#pragma unroll
    for (int nj = 0; nj < 12; ++nj) {
        const int c0 = n0 + nj*8 + 2*(lane & 3);
        const int mat = c0 >> 6, lc = c0 & 63;
        const float* bp = (mat == 0) ? bk : (mat == 1) ? bq : bv;
        const float b0 = bp[lc], b1 = bp[lc + 1];
        __nv_bfloat16* hp = (mat == 0) ? g_Khi : (mat == 1) ? g_Qhi : g_Vhi;
        __nv_bfloat16* lp = (mat == 0) ? g_Klo : (mat == 1) ? g_Qlo : g_Vlo;
#pragma unroll
        for (int mt = 0; mt < 2; ++mt)
#pragma unroll
            for (int h = 0; h < 2; ++h) {
                const int r = row0 + m0 + mt*16 + (lane >> 2) + h*8;
                float v0 = acc[mt][nj][h*2 + 0] + b0;
                float v1 = acc[mt][nj][h*2 + 1] + b1;
                __nv_bfloat16 h0 = __float2bfloat16(v0);
                __nv_bfloat16 h1 = __float2bfloat16(v1);
                uint32_t hv = (uint32_t)__bfloat16_as_ushort(h0) |
                              ((uint32_t)__bfloat16_as_ushort(h1) << 16);
                uint32_t lv = pack_bf16(v0 - __bfloat162float(h0),
                                        v1 - __bfloat162float(h1));
                size_t o = (size_t)r * HS_ + lc;
                *(uint32_t*)(hp + o) = hv;
                *(uint32_t*)(lp + o) = lv;
            }
    }
}

// ===========================================================================
// Attention: R14 structure + (a) K fragments hoisted out of the s-loop,
// (b) P-visibility via pairwise named barrier (warps wr and wr+4).
// ===========================================================================
#define OKHI  0u
#define OKLO  8192u
#define OBUF(b) (16384u + (uint32_t)(b) * 32768u)
#define OPHI  81920u
#define OPLO  90112u
#define ATTN_SMEM 98304u

__device__ __forceinline__ void ld_tile(char* sm, uint32_t dst,
                                        const __nv_bfloat16* __restrict__ src) {
#pragma unroll
    for (int i = 0; i < 2; ++i) {
        int idx = threadIdx.x + i * 256;
        int r = idx >> 3, cc = idx & 7;
        uint32_t off = (uint32_t)r * 128u + (uint32_t)((cc ^ (r & 7)) << 4);
        *(uint4*)(sm + dst + off) = *(const uint4*)(src + (size_t)r * HS_ + cc * 8);
    }
}

// GEMM1 with cached K fragments (A never reloaded).
__device__ __forceinline__ void gemm1_cached(uint32_t sb,
                                             const uint32_t kh[4][4],
                                             const uint32_t kl[4][4],
                                             uint32_t bHi, uint32_t bLo,
                                             int n0, float S[4][4])
{
    const int lane = threadIdx.x & 31;
    const int brow0 = n0 + (lane & 7) + ((lane >> 4) << 3);
    const int brow1 = brow0 + 16;
#pragma unroll
    for (int ks = 0; ks < 4; ++ks) {
        const int kgB = 2*ks + ((lane >> 3) & 1);
        uint32_t boff0 = (uint32_t)brow0*128u + (uint32_t)((kgB ^ (brow0 & 7)) << 4);
        uint32_t boff1 = (uint32_t)brow1*128u + (uint32_t)((kgB ^ (brow1 & 7)) << 4);
        uint32_t bh0[4], bh1[4], bl0[4], bl1[4];
        ldsm_x4(bh0, sb + bHi + boff0);
        ldsm_x4(bh1, sb + bHi + boff1);
        ldsm_x4(bl0, sb + bLo + boff0);
        ldsm_x4(bl1, sb + bLo + boff1);
#pragma unroll
        for (int j = 0; j < 4; ++j) {
            const uint32_t* bh = (j < 2) ? bh0 : bh1;
            const uint32_t* bl = (j < 2) ? bl0 : bl1;
            const int o = (j & 1) * 2;
            mma16816(S[j], kh[ks], bh + o);
            mma16816(S[j], kl[ks], bh + o);
            mma16816(S[j], kh[ks], bl + o);
        }
    }
}

__device__ __forceinline__ void gemm2_split(uint32_t sb, uint32_t pHi, uint32_t pLo,
                                            uint32_t vHi, uint32_t vLo,
                                            int m0, int n0, float O[4][4])
{
    const int lane = threadIdx.x & 31;
    const int arow = m0 + (lane & 15);
    const int g = lane >> 3, rr = lane & 7;
#pragma unroll
    for (int ks = 0; ks < 4; ++ks) {
        const int kgA = 2*ks + (lane >> 4);
        uint32_t aoff = (uint32_t)arow*128u + (uint32_t)((kgA ^ (arow & 7)) << 4);
        uint32_t ah[4], al[4];
        ldsm_x4(ah, sb + pHi + aoff);
        ldsm_x4(al, sb + pLo + aoff);
        const int s_row = ks*16 + ((g & 1) << 3) + rr;
        const uint32_t vrow = (uint32_t)s_row * 128u;
        const uint32_t sw = (uint32_t)(s_row & 7);
#pragma unroll
        for (int half = 0; half < 2; ++half) {
            const int h0 = n0 + half*16 + ((g >> 1) << 3);
            uint32_t voff = vrow + ((((uint32_t)h0 >> 3) ^ sw) << 4);
            uint32_t vh[4], vl[4];
            ldsm_x4_t(vh, sb + vHi + voff);
            ldsm_x4_t(vl, sb + vLo + voff);
#pragma unroll
            for (int jj = 0; jj < 2; ++jj) {
                const int j = half*2 + jj;
                mma16816(O[j], ah, vh + jj*2);
                mma16816(O[j], al, vh + jj*2);
                mma16816(O[j], ah, vl + jj*2);
            }
        }
    }
}

__device__ __forceinline__ void store_p(char* sm, int row, int col,
                                        float p0, float p1) {
    __nv_bfloat16 h0 = __float2bfloat16(p0), h1 = __float2bfloat16(p1);
    uint32_t hv = (uint32_t)__bfloat16_as_ushort(h0) |
                  ((uint32_t)__bfloat16_as_ushort(h1) << 16);
    uint32_t lv = pack_bf16(p0 - __bfloat162float(h0), p1 - __bfloat162float(h1));
    uint32_t g = (uint32_t)(col >> 3);
    uint32_t off = (uint32_t)row*128u + ((g ^ (uint32_t)(row & 7)) << 4)
                 + (uint32_t)((col & 7) * 2);
    *(uint32_t*)(sm + OPHI + off) = hv;
    *(uint32_t*)(sm + OPLO + off) = lv;
}

__global__ __launch_bounds__(256) void attn_kernel(float* __restrict__ out)
{
    extern __shared__ char sm[];
    const uint32_t sb = smem_u32(sm);
    const int tid  = threadIdx.x;
    const int lane = tid & 31;
    const int wid  = tid >> 5;
    const int wr = wid & 3, wc = wid >> 2;
    const int m0 = wr * 16, n0 = wc * 32;
    const int bb = blockIdx.y;

    const __nv_bfloat16* Khi = g_Khi + (size_t)bb * T_ * HS_;
    const __nv_bfloat16* Klo = g_Klo + (size_t)bb * T_ * HS_;
    const __nv_bfloat16* Qhi = g_Qhi + (size_t)bb * T_ * HS_;
    const __nv_bfloat16* Qlo = g_Qlo + (size_t)bb * T_ * HS_;
    const __nv_bfloat16* Vhi = g_Vhi + (size_t)bb * T_ * HS_;
    const __nv_bfloat16* Vlo = g_Vlo + (size_t)bb * T_ * HS_;

    for (int pass = 0; pass < 2; ++pass) {
        const int ti = pass ? 63 - (int)blockIdx.x : (int)blockIdx.x;
        const int t0 = ti * 64;

        __syncthreads();
        ld_tile(sm, OKHI, Khi + (size_t)t0 * HS_);
        ld_tile(sm, OKLO, Klo + (size_t)t0 * HS_);
        ld_tile(sm, OBUF(0) +     0u, Qhi);
        ld_tile(sm, OBUF(0) +  8192u, Qlo);
        ld_tile(sm, OBUF(0) + 16384u, Vhi);
        ld_tile(sm, OBUF(0) + 24576u, Vlo);

        float Oa[4][4];
#pragma unroll
        for (int j = 0; j < 4; ++j)
#pragma unroll
            for (int q = 0; q < 4; ++q) Oa[j][q] = 0.f;
        float l0 = 0.f, l1 = 0.f;
        const int rr0 = t0 + m0 + (lane >> 2), rr1 = rr0 + 8;

        __syncthreads();

        // hoist K fragments (pass-invariant A operands of GEMM1)
        uint32_t kfh[4][4], kfl[4][4];
        {
            const int arow = m0 + (lane & 15);
#pragma unroll
            for (int ks = 0; ks < 4; ++ks) {
                const int kgA = 2*ks + (lane >> 4);
                uint32_t aoff = (uint32_t)arow*128u
                              + (uint32_t)((kgA ^ (arow & 7)) << 4);
                ldsm_x4(kfh[ks], sb + OKHI + aoff);
                ldsm_x4(kfl[ks], sb + OKLO + aoff);
            }
        }

        for (int s0 = 0, it = 0; s0 <= t0; s0 += 64, ++it) {
            const uint32_t cb = OBUF(it & 1);
            const uint32_t nb = OBUF(1 - (it & 1));
            const int sn = s0 + 64;
            const bool hasNext = (sn <= t0);

            if (hasNext) {
#pragma unroll
                for (int t4 = 0; t4 < 4; ++t4) {
                    const __nv_bfloat16* s4 =
                        (t4 == 0 ? Qhi : t4 == 1 ? Qlo : t4 == 2 ? Vhi : Vlo)
                        + (size_t)sn * HS_;
                    const uint32_t db = sb + nb + (uint32_t)t4 * 8192u;
#pragma unroll
                    for (int i = 0; i < 2; ++i) {
                        int idx = tid + i * 256, r = idx >> 3, cc = idx & 7;
                        uint32_t off = (uint32_t)r * 128u
                                     + (uint32_t)((cc ^ (r & 7)) << 4);
                        CP_ASYNC16(db + off, s4 + (size_t)r * HS_ + cc * 8);
                    }
                }
                CP_COMMIT();
            }

            float S[4][4];
#pragma unroll
            for (int j = 0; j < 4; ++j)
#pragma unroll
                for (int q = 0; q < 4; ++q) S[j][q] = 0.f;
            gemm1_cached(sb, kfh, kfl, cb, cb + 8192u, n0, S);

            const bool diag = (s0 == t0);
#pragma unroll
            for (int j = 0; j < 4; ++j) {
                const int cl = n0 + 8*j + 2*(lane & 3);
                const int cg = s0 + cl;
                float p00 = __expf(S[j][0]);
                float p01 = __expf(S[j][1]);
                float p10 = __expf(S[j][2]);
                float p11 = __expf(S[j][3]);
                if (diag) {
                    if (cg     > rr0) p00 = 0.f;
                    if (cg + 1 > rr0) p01 = 0.f;
                    if (cg     > rr1) p10 = 0.f;
                    if (cg + 1 > rr1) p11 = 0.f;
                }
                l0 += p00 + p01;
                l1 += p10 + p11;
                store_p(sm, m0 + (lane >> 2),     cl, p00, p01);
                store_p(sm, m0 + (lane >> 2) + 8, cl, p10, p11);
            }
            // P rows for warp-pair {wr, wr+4}: pairwise named barrier (64 thr)
            asm volatile("bar.sync %0, 64;" :: "r"(wr + 1) : "memory");

            gemm2_split(sb, OPHI, OPLO, cb + 16384u, cb + 24576u, m0, n0, Oa);

            if (hasNext) CP_WAIT0();
            __syncthreads();                   // buffers reusable; bounds skew
        }

        // epilogue: reduce l across lanes + wc warps, scale, store
        float* l_sm = (float*)(sm + OKHI);
        l0 += __shfl_xor_sync(0xffffffffu, l0, 1);
        l0 += __shfl_xor_sync(0xffffffffu, l0, 2);
        l1 += __shfl_xor_sync(0xffffffffu, l1, 1);
        l1 += __shfl_xor_sync(0xffffffffu, l1, 2);
        if ((lane & 3) == 0) {
            l_sm[wc*64 + m0 + (lane >> 2)]     = l0;
            l_sm[wc*64 + m0 + (lane >> 2) + 8] = l1;
        }
        __syncthreads();
        {
            const int rl = m0 + (lane >> 2);
            const float inv0 = 1.f / (l_sm[rl]     + l_sm[64 + rl]);
            const float inv1 = 1.f / (l_sm[rl + 8] + l_sm[64 + rl + 8]);
            float2* b0p = (float2*)(out + ((size_t)bb * T_ + t0 + rl)     * HS_);
            float2* b1p = (float2*)(out + ((size_t)bb * T_ + t0 + rl + 8) * HS_);
#pragma unroll
            for (int j = 0; j < 4; ++j) {
                const int c = n0 + 8*j + 2*(lane & 3);
                b0p[c >> 1] = make_float2(Oa[j][0]*inv0, Oa[j][1]*inv0);
                b1p[c >> 1] = make_float2(Oa[j][2]*inv1, Oa[j][3]*inv1);
            }
        }
    }
}

// ---------------------------------------------------------------------------
extern "C" void kernel_launch(void* const* d_in, const int* in_sizes, int n_in,
                              void* d_out, int out_size)
{
    (void)in_sizes; (void)n_in; (void)out_size;
    const float* x  = (const float*)d_in[0];
    const float* Wk = (const float*)d_in[1];
    const float* bk = (const float*)d_in[2];
    const float* Wq = (const float*)d_in[3];
    const float* bq = (const float*)d_in[4];
    const float* Wv = (const float*)d_in[5];
    const float* bv = (const float*)d_in[6];
    float* out = (float*)d_out;

    cudaFuncSetAttribute(proj_kernel,
                         cudaFuncAttributeMaxDynamicSharedMemorySize, PROJ_SMEM);
    cudaFuncSetAttribute(attn_kernel,
                         cudaFuncAttributeMaxDynamicSharedMemorySize, ATTN_SMEM);

    wconv_kernel<<<192, 256>>>(Wk, Wq, Wv);
    proj_kernel<<<BT_/128, 256, PROJ_SMEM>>>(x, bk, bq, bv);
    attn_kernel<<<dim3(32, B_), 256, ATTN_SMEM>>>(out);
}